// round 1
// baseline (speedup 1.0000x reference)
#include <cuda_runtime.h>

#define G 1024
#define BATCH 4

// Edge counts (fixed, derived from the reference's grid adjacency for G=1024):
// diag: 1023*1023, horiz: 1022*1023, vert: 1023*1022
// total E = 1023*(1023+1022+1022) = 3,137,541 ; N = B*E = 12,550,164
#define N_TOTAL 12550164.0

__device__ double g_acc;

__global__ void nc_zero_kernel() { g_acc = 0.0; }

__device__ __forceinline__ float edge_loss(float3 v0, float3 v1, float3 a, float3 b) {
    float ex = v1.x - v0.x, ey = v1.y - v0.y, ez = v1.z - v0.z;
    float ax = a.x - v0.x,  ay = a.y - v0.y,  az = a.z - v0.z;
    float bx = b.x - v0.x,  by = b.y - v0.y,  bz = b.z - v0.z;
    // n0 = cross(e, a-v0)
    float n0x = ey*az - ez*ay;
    float n0y = ez*ax - ex*az;
    float n0z = ex*ay - ey*ax;
    // n1 = -cross(e, b-v0) = cross(b-v0, e)
    float n1x = by*ez - bz*ey;
    float n1y = bz*ex - bx*ez;
    float n1z = bx*ey - by*ex;
    float dot = n0x*n1x + n0y*n1y + n0z*n1z;
    float q0  = n0x*n0x + n0y*n0y + n0z*n0z;
    float q1  = n1x*n1x + n1y*n1y + n1z*n1z;
    q0 = fmaxf(q0, 1e-16f);   // == max(|n0|, 1e-8)^2
    q1 = fmaxf(q1, 1e-16f);
    return 1.0f - dot * rsqrtf(q0 * q1);
}

__device__ __forceinline__ float3 ldv(const float* __restrict__ base, int r, int c) {
    const float* p = base + ((size_t)r * G + c) * 3;
    return make_float3(p[0], p[1], p[2]);
}

__global__ void __launch_bounds__(256)
nc_loss_kernel(const float* __restrict__ x) {
    const int c  = blockIdx.x * blockDim.x + threadIdx.x;
    const int r  = blockIdx.y;          // 0 .. G-2
    const int bb = blockIdx.z;          // batch

    float sum = 0.0f;
    if (c < G - 1) {
        const float* base = x + (size_t)bb * (size_t)G * G * 3;
        float3 p00 = ldv(base, r,   c);
        float3 p01 = ldv(base, r,   c + 1);
        float3 p10 = ldv(base, r + 1, c);
        float3 p11 = ldv(base, r + 1, c + 1);

        // diagonal edge of quad (r,c): v0=(r,c), v1=(r+1,c+1), a=(r,c+1), b=(r+1,c)
        sum += edge_loss(p00, p11, p01, p10);

        if (r >= 1) {
            // horizontal interior edge: v0=(r,c), v1=(r,c+1), a=(r+1,c+1), b=(r-1,c)
            float3 pm = ldv(base, r - 1, c);
            sum += edge_loss(p00, p01, p11, pm);
        }
        if (c >= 1) {
            // vertical interior edge: v0=(r,c), v1=(r+1,c), a=(r+1,c+1), b=(r,c-1)
            float3 pl = ldv(base, r, c - 1);
            sum += edge_loss(p00, p10, p11, pl);
        }
    }

    // ---- block reduction (warp shuffle -> shared -> one double atomic) ----
    #pragma unroll
    for (int off = 16; off > 0; off >>= 1)
        sum += __shfl_down_sync(0xFFFFFFFFu, sum, off);

    __shared__ float warp_sums[8];
    const int lane = threadIdx.x & 31;
    const int wid  = threadIdx.x >> 5;
    if (lane == 0) warp_sums[wid] = sum;
    __syncthreads();

    if (wid == 0) {
        float s = (lane < (blockDim.x >> 5)) ? warp_sums[lane] : 0.0f;
        #pragma unroll
        for (int off = 4; off > 0; off >>= 1)
            s += __shfl_down_sync(0xFFFFFFFFu, s, off);
        if (lane == 0) atomicAdd(&g_acc, (double)s);
    }
}

__global__ void nc_finalize_kernel(float* __restrict__ out) {
    out[0] = (float)(g_acc / N_TOTAL);
}

extern "C" void kernel_launch(void* const* d_in, const int* in_sizes, int n_in,
                              void* d_out, int out_size) {
    const float* x = (const float*)d_in[0];
    float* out = (float*)d_out;

    nc_zero_kernel<<<1, 1>>>();

    dim3 block(256, 1, 1);
    dim3 grid((G - 1 + 255) / 256, G - 1, BATCH);   // (4, 1023, 4)
    nc_loss_kernel<<<grid, block>>>(x);

    nc_finalize_kernel<<<1, 1>>>(out);
}

// round 2
// speedup vs baseline: 1.1793x; 1.1793x over previous
#include <cuda_runtime.h>

#define G 1024
#define BATCH 4
#define ROWS_PER_CHUNK 16

// E = 1023*1023 + 1022*1023 + 1023*1022 = 3,137,541 ; N = B*E
#define N_TOTAL 12550164.0

__device__ double g_acc = 0.0;
__device__ unsigned int g_done = 0;

__device__ __forceinline__ float edge_loss(float3 v0, float3 v1, float3 a, float3 b) {
    float ex = v1.x - v0.x, ey = v1.y - v0.y, ez = v1.z - v0.z;
    float ax = a.x - v0.x,  ay = a.y - v0.y,  az = a.z - v0.z;
    float bx = b.x - v0.x,  by = b.y - v0.y,  bz = b.z - v0.z;
    // n0 = cross(e, a-v0)
    float n0x = ey*az - ez*ay;
    float n0y = ez*ax - ex*az;
    float n0z = ex*ay - ey*ax;
    // n1 = -cross(e, b-v0) = cross(b-v0, e)
    float n1x = by*ez - bz*ey;
    float n1y = bz*ex - bx*ez;
    float n1z = bx*ey - by*ex;
    float dot = n0x*n1x + n0y*n1y + n0z*n1z;
    float q0  = n0x*n0x + n0y*n0y + n0z*n0z;
    float q1  = n1x*n1x + n1y*n1y + n1z*n1z;
    q0 = fmaxf(q0, 1e-16f);   // == max(|n0|, 1e-8)^2
    q1 = fmaxf(q1, 1e-16f);
    return 1.0f - dot * rsqrtf(q0 * q1);
}

__device__ __forceinline__ float3 ldv(const float* __restrict__ base, int r, int c) {
    const float* p = base + ((size_t)r * G + c) * 3;
    return make_float3(p[0], p[1], p[2]);
}

__global__ void __launch_bounds__(256)
nc_fused_kernel(const float* __restrict__ x, float* __restrict__ out,
                unsigned int nblocks) {
    const int c  = blockIdx.x * blockDim.x + threadIdx.x;   // column (0..1022 valid)
    const int r0 = blockIdx.y * ROWS_PER_CHUNK;             // first quad row of chunk
    const int bb = blockIdx.z;                              // batch

    float sum = 0.0f;
    if (c < G - 1) {
        const float* base = x + (size_t)bb * (size_t)G * G * 3;
        const int r1 = min(r0 + ROWS_PER_CHUNK, G - 1);

        // prologue: row r0 state
        float3 p00 = ldv(base, r0, c);
        float3 p01 = ldv(base, r0, c + 1);
        float3 pl  = (c >= 1) ? ldv(base, r0, c - 1) : make_float3(0.f, 0.f, 0.f);
        float3 pm  = (r0 >= 1) ? ldv(base, r0 - 1, c) : make_float3(0.f, 0.f, 0.f);

        for (int r = r0; r < r1; ++r) {
            // load only the new row r+1
            float3 p10 = ldv(base, r + 1, c);
            float3 p11 = ldv(base, r + 1, c + 1);
            float3 pln = (c >= 1) ? ldv(base, r + 1, c - 1) : make_float3(0.f, 0.f, 0.f);

            // diagonal: v0=(r,c), v1=(r+1,c+1), a=(r,c+1), b=(r+1,c)
            sum += edge_loss(p00, p11, p01, p10);
            // horizontal (r>=1): v0=(r,c), v1=(r,c+1), a=(r+1,c+1), b=(r-1,c)
            if (r >= 1) sum += edge_loss(p00, p01, p11, pm);
            // vertical (c>=1): v0=(r,c), v1=(r+1,c), a=(r+1,c+1), b=(r,c-1)
            if (c >= 1) sum += edge_loss(p00, p10, p11, pl);

            // roll registers down one row
            pm = p00; p00 = p10; p01 = p11; pl = pln;
        }
    }

    // ---- block reduction ----
    #pragma unroll
    for (int off = 16; off > 0; off >>= 1)
        sum += __shfl_down_sync(0xFFFFFFFFu, sum, off);

    __shared__ float warp_sums[8];
    const int lane = threadIdx.x & 31;
    const int wid  = threadIdx.x >> 5;
    if (lane == 0) warp_sums[wid] = sum;
    __syncthreads();

    __shared__ bool is_last;
    if (wid == 0) {
        float s = (lane < (blockDim.x >> 5)) ? warp_sums[lane] : 0.0f;
        #pragma unroll
        for (int off = 4; off > 0; off >>= 1)
            s += __shfl_down_sync(0xFFFFFFFFu, s, off);
        if (lane == 0) {
            atomicAdd(&g_acc, (double)s);
            __threadfence();
            unsigned int done = atomicInc(&g_done, nblocks - 1);
            is_last = (done == nblocks - 1);
        }
    }
    __syncthreads();

    // last block finalizes: write result, reset accumulators for next replay
    if (is_last && threadIdx.x == 0) {
        double acc = atomicAdd(&g_acc, 0.0);   // coherent read
        out[0] = (float)(acc / N_TOTAL);
        __threadfence();
        g_acc = 0.0;                            // g_done already wrapped to 0 by atomicInc
    }
}

extern "C" void kernel_launch(void* const* d_in, const int* in_sizes, int n_in,
                              void* d_out, int out_size) {
    const float* x = (const float*)d_in[0];
    float* out = (float*)d_out;

    dim3 block(256, 1, 1);
    dim3 grid((G - 1 + 255) / 256,                       // 4 col-blocks
              (G - 1 + ROWS_PER_CHUNK - 1) / ROWS_PER_CHUNK,  // 64 row chunks
              BATCH);                                     // 4
    unsigned int nblocks = grid.x * grid.y * grid.z;
    nc_fused_kernel<<<grid, block>>>(x, out, nblocks);
}

// round 3
// speedup vs baseline: 1.1819x; 1.0022x over previous
#include <cuda_runtime.h>

#define G 1024
#define BATCH 4
#define ROWS_PER_CHUNK 23
#define GRID_Y ((G - 1 + ROWS_PER_CHUNK - 1) / ROWS_PER_CHUNK)   // 45

// E = 1023*1023 + 1022*1023 + 1023*1022 = 3,137,541 ; N = B*E
#define N_TOTAL 12550164.0

__device__ double g_acc = 0.0;
__device__ unsigned int g_done = 0;

__device__ __forceinline__ float edge_loss(float3 v0, float3 v1, float3 a, float3 b) {
    float ex = v1.x - v0.x, ey = v1.y - v0.y, ez = v1.z - v0.z;
    float ax = a.x - v0.x,  ay = a.y - v0.y,  az = a.z - v0.z;
    float bx = b.x - v0.x,  by = b.y - v0.y,  bz = b.z - v0.z;
    // n0 = cross(e, a-v0)
    float n0x = fmaf(ey, az, -ez*ay);
    float n0y = fmaf(ez, ax, -ex*az);
    float n0z = fmaf(ex, ay, -ey*ax);
    // n1 = -cross(e, b-v0) = cross(b-v0, e)
    float n1x = fmaf(by, ez, -bz*ey);
    float n1y = fmaf(bz, ex, -bx*ez);
    float n1z = fmaf(bx, ey, -by*ex);
    float dot = fmaf(n0x, n1x, fmaf(n0y, n1y, n0z*n1z));
    float q0  = fmaf(n0x, n0x, fmaf(n0y, n0y, n0z*n0z));
    float q1  = fmaf(n1x, n1x, fmaf(n1y, n1y, n1z*n1z));
    q0 = fmaxf(q0, 1e-16f);   // == max(|n0|, 1e-8)^2
    q1 = fmaxf(q1, 1e-16f);
    return 1.0f - dot * rsqrtf(q0 * q1);
}

__device__ __forceinline__ float3 ldv(const float* __restrict__ p) {
    return make_float3(p[0], p[1], p[2]);
}

__global__ void __launch_bounds__(256, 5)
nc_fused_kernel(const float* __restrict__ x, float* __restrict__ out,
                unsigned int nblocks) {
    const int c  = blockIdx.x * blockDim.x + threadIdx.x;   // column (0..1022 valid)
    const int r0 = blockIdx.y * ROWS_PER_CHUNK;             // first quad row of chunk
    const int bb = blockIdx.z;                              // batch

    float sum = 0.0f;
    if (c < G - 1) {
        const float* __restrict__ base = x + (size_t)bb * (size_t)G * G * 3;
        const int r1 = min(r0 + ROWS_PER_CHUNK, G - 1);
        const bool has_left = (c >= 1);

        // row pointer for current row r0, at column c
        const float* __restrict__ row = base + ((size_t)r0 * G + c) * 3;

        // prologue: row r0 state
        float3 p00 = ldv(row);
        float3 p01 = ldv(row + 3);
        float3 pl  = has_left ? ldv(row - 3) : make_float3(0.f, 0.f, 0.f);
        float3 pm  = (r0 >= 1) ? ldv(row - G * 3) : make_float3(0.f, 0.f, 0.f);

        for (int r = r0; r < r1; ++r) {
            const float* __restrict__ nrow = row + G * 3;   // row r+1
            float3 p10 = ldv(nrow);
            float3 p11 = ldv(nrow + 3);
            float3 pln = has_left ? ldv(nrow - 3) : make_float3(0.f, 0.f, 0.f);

            // diagonal: v0=(r,c), v1=(r+1,c+1), a=(r,c+1), b=(r+1,c)
            sum += edge_loss(p00, p11, p01, p10);
            // horizontal (r>=1): v0=(r,c), v1=(r,c+1), a=(r+1,c+1), b=(r-1,c)
            if (r >= 1) sum += edge_loss(p00, p01, p11, pm);
            // vertical (c>=1): v0=(r,c), v1=(r+1,c), a=(r+1,c+1), b=(r,c-1)
            if (has_left) sum += edge_loss(p00, p10, p11, pl);

            // roll registers down one row
            pm = p00; p00 = p10; p01 = p11; pl = pln;
            row = nrow;
        }
    }

    // ---- block reduction ----
    #pragma unroll
    for (int off = 16; off > 0; off >>= 1)
        sum += __shfl_down_sync(0xFFFFFFFFu, sum, off);

    __shared__ float warp_sums[8];
    const int lane = threadIdx.x & 31;
    const int wid  = threadIdx.x >> 5;
    if (lane == 0) warp_sums[wid] = sum;
    __syncthreads();

    __shared__ bool is_last;
    if (wid == 0) {
        float s = (lane < (blockDim.x >> 5)) ? warp_sums[lane] : 0.0f;
        #pragma unroll
        for (int off = 4; off > 0; off >>= 1)
            s += __shfl_down_sync(0xFFFFFFFFu, s, off);
        if (lane == 0) {
            atomicAdd(&g_acc, (double)s);
            __threadfence();
            unsigned int done = atomicInc(&g_done, nblocks - 1);
            is_last = (done == nblocks - 1);
        }
    }
    __syncthreads();

    // last block finalizes: write result, reset accumulator for next replay
    if (is_last && threadIdx.x == 0) {
        double acc = atomicAdd(&g_acc, 0.0);   // coherent read
        out[0] = (float)(acc / N_TOTAL);
        __threadfence();
        g_acc = 0.0;                            // g_done wrapped to 0 via atomicInc
    }
}

extern "C" void kernel_launch(void* const* d_in, const int* in_sizes, int n_in,
                              void* d_out, int out_size) {
    const float* x = (const float*)d_in[0];
    float* out = (float*)d_out;

    dim3 block(256, 1, 1);
    dim3 grid((G - 1 + 255) / 256,   // 4 col-blocks
              GRID_Y,                // 45 row chunks
              BATCH);                // 4  -> 720 blocks total (one wave @ 5 CTA/SM)
    unsigned int nblocks = grid.x * grid.y * grid.z;
    nc_fused_kernel<<<grid, block>>>(x, out, nblocks);
}